// round 1
// baseline (speedup 1.0000x reference)
#include <cuda_runtime.h>

// ---------------- problem constants ----------------
#define B       2
#define T       32768
#define BT      (B*T)           // 65536
#define HID     128
#define R2      16384           // 128*128
#define POOL_N  (3*B*R2*128)    // 12,582,912
#define CNT_N   (3*B*R2)

// ---------------- scratch (device globals; no allocs) ----------------
__device__ float g_x[BT*256];       // block input (concat)  67MB
__device__ float g_h[BT*128];       // hidden / c            33MB
__device__ float g_net[BT*128];     // block output          33MB
__device__ float g_pool[POOL_N];    // per-plane per-cell max / sum  50MB
__device__ float g_cnt[CNT_N];
__device__ int   g_idx[3][BT];

// ---------------- index computation (matches jax exactly) ----------------
__global__ void k_index(const float* __restrict__ p) {
    int t = blockIdx.x * blockDim.x + threadIdx.x;
    if (t >= BT) return;
    float x = p[t*3+0], y = p[t*3+1], z = p[t*3+2];
    float cu[3] = {x, x, y};   // xz, xy, yz : first dim
    float cv[3] = {z, y, z};   // second dim
    const float hi = (float)(1.0 - 1e-5);
    #pragma unroll
    for (int k = 0; k < 3; k++) {
        float u = cu[k] / 1.101f + 0.5f;
        float v = cv[k] / 1.101f + 0.5f;
        u = fminf(fmaxf(u, 0.0f), hi);
        v = fminf(fmaxf(v, 0.0f), hi);
        int gu = (int)(u * 128.0f);
        int gv = (int)(v * 128.0f);
        g_idx[k][t] = gu + 128 * gv;
    }
}

// ---------------- fc_pos: (BT,3) @ (3,256) + b ----------------
__global__ void k_fcpos(const float* __restrict__ p, const float* __restrict__ W,
                        const float* __restrict__ bias) {
    int i = blockIdx.x * blockDim.x + threadIdx.x;   // BT*256
    int t = i >> 8, n = i & 255;
    float p0 = p[t*3+0], p1 = p[t*3+1], p2 = p[t*3+2];
    g_x[i] = p0 * W[n] + p1 * W[256+n] + p2 * W[512+n] + bias[n];
}

// ---------------- fp32 GEMM: C[M,128] = f(A[M,K]) @ W[K,128] (+bias) (+D) ----
// BM=128, BN=128 (full N), BK=16, 256 threads, 8x8 per thread.
template<int K, bool RELU_A, bool ADD_D>
__global__ __launch_bounds__(256, 2)
void k_gemm(const float* __restrict__ A, const float* __restrict__ W,
            const float* __restrict__ bias, const float* __restrict__ D,
            float* __restrict__ C) {
    __shared__ float As[16][132];   // transposed A tile, padded (132*4 % 16 == 0)
    __shared__ float Bs[16][128];
    const int tid = threadIdx.x;
    const int m0  = blockIdx.x * 128;
    const int tx  = tid & 15;       // n sub-tile
    const int ty  = tid >> 4;       // m sub-tile
    float acc[8][8] = {};

    for (int k0 = 0; k0 < K; k0 += 16) {
        // load A tile (128 rows x 16 k) transposed into As[k][m]
        #pragma unroll
        for (int l = 0; l < 2; l++) {
            int li = tid + l * 256;         // 0..511 float4 slots
            int r  = li >> 2;               // row 0..127
            int c4 = (li & 3) * 4;          // k 0,4,8,12
            float4 v = *(const float4*)&A[(size_t)(m0 + r) * K + k0 + c4];
            if (RELU_A) {
                v.x = fmaxf(v.x, 0.f); v.y = fmaxf(v.y, 0.f);
                v.z = fmaxf(v.z, 0.f); v.w = fmaxf(v.w, 0.f);
            }
            As[c4+0][r] = v.x; As[c4+1][r] = v.y;
            As[c4+2][r] = v.z; As[c4+3][r] = v.w;
        }
        // load W tile (16 x 128)
        #pragma unroll
        for (int l = 0; l < 2; l++) {
            int li = tid + l * 256;         // 0..511 float4 slots
            int r  = li >> 5;               // k row 0..15
            int c4 = (li & 31) * 4;
            *(float4*)&Bs[r][c4] = *(const float4*)&W[(size_t)(k0 + r) * 128 + c4];
        }
        __syncthreads();
        #pragma unroll
        for (int kk = 0; kk < 16; kk++) {
            float a[8], b[8];
            *(float4*)(a)   = *(float4*)&As[kk][ty*8];
            *(float4*)(a+4) = *(float4*)&As[kk][ty*8+4];
            *(float4*)(b)   = *(float4*)&Bs[kk][tx*8];
            *(float4*)(b+4) = *(float4*)&Bs[kk][tx*8+4];
            #pragma unroll
            for (int i = 0; i < 8; i++)
                #pragma unroll
                for (int j = 0; j < 8; j++)
                    acc[i][j] += a[i] * b[j];
        }
        __syncthreads();
    }

    #pragma unroll
    for (int i = 0; i < 8; i++) {
        int m = m0 + ty*8 + i;
        #pragma unroll
        for (int j = 0; j < 8; j += 4) {
            int n = tx*8 + j;
            float4 r;
            r.x = acc[i][j]; r.y = acc[i][j+1]; r.z = acc[i][j+2]; r.w = acc[i][j+3];
            if (bias) {
                r.x += bias[n]; r.y += bias[n+1]; r.z += bias[n+2]; r.w += bias[n+3];
            }
            if (ADD_D) {
                float4 d = *(const float4*)&D[(size_t)m*128 + n];
                r.x += d.x; r.y += d.y; r.z += d.z; r.w += d.w;
            }
            *(float4*)&C[(size_t)m*128 + n] = r;
        }
    }
}

// ---------------- pool reset to -inf ----------------
__global__ void k_pool_neg_inf() {
    int i = blockIdx.x * blockDim.x + threadIdx.x;
    if (i < POOL_N) ((int*)g_pool)[i] = 0xFF800000;   // -inf
}

// ---------------- scatter max of g_net into pools ----------------
__global__ void k_scatter_max() {
    int i = blockIdx.x * blockDim.x + threadIdx.x;   // BT*128
    int t = i >> 7, f = i & 127;
    int b = t >> 15;
    float v = g_net[i];
    #pragma unroll
    for (int k = 0; k < 3; k++) {
        float* addr = &g_pool[(size_t)((k*B + b) * R2 + g_idx[k][t]) * 128 + f];
        if (v >= 0.0f) atomicMax((int*)addr, __float_as_int(v));
        else           atomicMin((unsigned int*)addr, __float_as_uint(v));
    }
}

// ---------------- gather pooled + concat into g_x ----------------
__global__ void k_gather_concat() {
    int i = blockIdx.x * blockDim.x + threadIdx.x;   // BT*128
    int t = i >> 7, f = i & 127;
    int b = t >> 15;
    float s = 0.0f;
    #pragma unroll
    for (int k = 0; k < 3; k++)
        s += g_pool[(size_t)((k*B + b) * R2 + g_idx[k][t]) * 128 + f];
    g_x[(size_t)t*256 + f]       = g_net[i];
    g_x[(size_t)t*256 + 128 + f] = s;
}

// ---------------- zero pool + counts ----------------
__global__ void k_zero() {
    int i = blockIdx.x * blockDim.x + threadIdx.x;
    if (i < POOL_N) g_pool[i] = 0.0f;
    if (i < CNT_N)  g_cnt[i]  = 0.0f;
}

// ---------------- scatter sum of c (g_h) into pools + counts ----------------
__global__ void k_scatter_sum() {
    int i = blockIdx.x * blockDim.x + threadIdx.x;   // BT*128
    int t = i >> 7, f = i & 127;
    int b = t >> 15;
    float v = g_h[i];
    #pragma unroll
    for (int k = 0; k < 3; k++) {
        int cell = g_idx[k][t];
        atomicAdd(&g_pool[(size_t)((k*B + b) * R2 + cell) * 128 + f], v);
        if (f == 0) atomicAdd(&g_cnt[(k*B + b) * R2 + cell], 1.0f);
    }
}

// ---------------- finalize: divide by count, transpose to (3,B,C,R2) ------
__global__ void k_finalize(float* __restrict__ out) {
    int i = blockIdx.x * blockDim.x + threadIdx.x;   // POOL_N, [kb][f][cell]
    if (i >= POOL_N) return;
    int cell = i & (R2 - 1);
    int f    = (i >> 14) & 127;
    int kb   = i >> 21;
    float cnt = g_cnt[kb * R2 + cell];
    float v = g_pool[(size_t)(kb * R2 + cell) * 128 + f] / fmaxf(cnt, 1.0f);
    out[i] = v;    // out layout (3,B,128,R2) with cell fastest == i
}

// ---------------- host orchestration ----------------
extern "C" void kernel_launch(void* const* d_in, const int* in_sizes, int n_in,
                              void* d_out, int out_size) {
    const float* p        = (const float*)d_in[0];
    const float* fc_pos_W = (const float*)d_in[1];
    const float* fc_pos_b = (const float*)d_in[2];
    const float* bW0      = (const float*)d_in[3];  // (5,256,128)
    const float* bb0      = (const float*)d_in[4];  // (5,128)
    const float* bW1      = (const float*)d_in[5];  // (5,128,128)
    const float* bb1      = (const float*)d_in[6];  // (5,128)
    const float* bWs      = (const float*)d_in[7];  // (5,256,128)
    const float* fc_c_W   = (const float*)d_in[8];  // (128,128)
    const float* fc_c_b   = (const float*)d_in[9];  // (128,)
    float* out = (float*)d_out;

    float* gx   = nullptr; cudaGetSymbolAddress((void**)&gx,   g_x);
    float* gh   = nullptr; cudaGetSymbolAddress((void**)&gh,   g_h);
    float* gnet = nullptr; cudaGetSymbolAddress((void**)&gnet, g_net);

    const int TPB = 256;
    const int GEMM_GRID = BT / 128;          // 512

    // indices
    k_index<<<BT / TPB, TPB>>>(p);
    // fc_pos -> g_x (BT,256)
    k_fcpos<<<(BT * 256) / TPB, TPB>>>(p, fc_pos_W, fc_pos_b);

    // block 0 (no pooling)
    k_gemm<256, true,  false><<<GEMM_GRID, TPB>>>(gx, bW0, bb0, nullptr, gh);
    k_gemm<128, true,  false><<<GEMM_GRID, TPB>>>(gh, bW1, bb1, nullptr, gnet);
    k_gemm<256, false, true ><<<GEMM_GRID, TPB>>>(gx, bWs, nullptr, gnet, gnet);

    // blocks 1..4 with pooling
    for (int blk = 1; blk < 5; blk++) {
        k_pool_neg_inf<<<POOL_N / TPB, TPB>>>();
        k_scatter_max<<<(BT * 128) / TPB, TPB>>>();
        k_gather_concat<<<(BT * 128) / TPB, TPB>>>();
        const float* W0 = bW0 + (size_t)blk * 256 * 128;
        const float* b0 = bb0 + (size_t)blk * 128;
        const float* W1 = bW1 + (size_t)blk * 128 * 128;
        const float* b1 = bb1 + (size_t)blk * 128;
        const float* Ws = bWs + (size_t)blk * 256 * 128;
        k_gemm<256, true,  false><<<GEMM_GRID, TPB>>>(gx, W0, b0, nullptr, gh);
        k_gemm<128, true,  false><<<GEMM_GRID, TPB>>>(gh, W1, b1, nullptr, gnet);
        k_gemm<256, false, true ><<<GEMM_GRID, TPB>>>(gx, Ws, nullptr, gnet, gnet);
    }

    // fc_c -> g_h  (c features)
    k_gemm<128, false, false><<<GEMM_GRID, TPB>>>(gnet, fc_c_W, fc_c_b, nullptr, gh);

    // scatter mean into output
    k_zero<<<POOL_N / TPB, TPB>>>();
    k_scatter_sum<<<(BT * 128) / TPB, TPB>>>();
    k_finalize<<<POOL_N / TPB, TPB>>>(out);
}

// round 2
// speedup vs baseline: 1.0226x; 1.0226x over previous
#include <cuda_runtime.h>

// ---------------- problem constants ----------------
#define B       2
#define T       32768
#define BT      (B*T)           // 65536
#define HID     128
#define R2      16384           // 128*128
#define POOL_N  (3*B*R2*128)    // 12,582,912
#define CNT_N   (3*B*R2)

// ---------------- scratch (device globals; no allocs) ----------------
__device__ float g_x[BT*256];       // block input (concat)
__device__ float g_h[BT*128];       // hidden / c
__device__ float g_net[BT*128];     // block output
__device__ float g_pool[POOL_N];    // per-plane per-cell max / sum
__device__ float g_cnt[CNT_N];
__device__ int   g_idx[3][BT];

// ---------------- f32x2 helpers (FFMA2 — ptxas never emits this) ------------
__device__ __forceinline__ unsigned long long pack2(float x) {
    unsigned long long r;
    asm("mov.b64 %0, {%1, %1};" : "=l"(r) : "r"(__float_as_uint(x)));
    return r;
}
__device__ __forceinline__ void ffma2(unsigned long long& acc,
                                      unsigned long long a, unsigned long long b) {
    asm("fma.rn.f32x2 %0, %1, %2, %0;" : "+l"(acc) : "l"(a), "l"(b));
}

// ---------------- index computation (matches jax exactly) ----------------
__global__ void k_index(const float* __restrict__ p) {
    int t = blockIdx.x * blockDim.x + threadIdx.x;
    if (t >= BT) return;
    float x = p[t*3+0], y = p[t*3+1], z = p[t*3+2];
    float cu[3] = {x, x, y};   // xz, xy, yz : first dim
    float cv[3] = {z, y, z};   // second dim
    const float hi = (float)(1.0 - 1e-5);
    #pragma unroll
    for (int k = 0; k < 3; k++) {
        float u = cu[k] / 1.101f + 0.5f;
        float v = cv[k] / 1.101f + 0.5f;
        u = fminf(fmaxf(u, 0.0f), hi);
        v = fminf(fmaxf(v, 0.0f), hi);
        int gu = (int)(u * 128.0f);
        int gv = (int)(v * 128.0f);
        g_idx[k][t] = gu + 128 * gv;
    }
}

// ---------------- fc_pos: (BT,3) @ (3,256) + b ----------------
__global__ void k_fcpos(const float* __restrict__ p, const float* __restrict__ W,
                        const float* __restrict__ bias) {
    int i = blockIdx.x * blockDim.x + threadIdx.x;   // BT*256
    int t = i >> 8, n = i & 255;
    float p0 = p[t*3+0], p1 = p[t*3+1], p2 = p[t*3+2];
    g_x[i] = p0 * W[n] + p1 * W[256+n] + p2 * W[512+n] + bias[n];
}

// ---------------- fp32 GEMM: C[M,128] = f(A[M,K]) @ W[K,128] (+bias) (+D) ----
// BM=128, BN=128 (full N), BK=16, 256 threads, 8x8 per thread.
// Inner loop in packed f32x2 (FFMA2); register-staged prefetch hides LDG latency.
template<int K, bool RELU_A, bool ADD_D>
__global__ __launch_bounds__(256, 2)
void k_gemm(const float* __restrict__ A, const float* __restrict__ W,
            const float* __restrict__ bias, const float* __restrict__ D,
            float* __restrict__ C) {
    __shared__ float As[16][132];   // transposed A tile, padded (528B rows, 16B-aligned)
    __shared__ float Bs[16][132];
    const int tid = threadIdx.x;
    const int m0  = blockIdx.x * 128;
    const int tx  = tid & 15;       // n sub-tile
    const int ty  = tid >> 4;       // m sub-tile

    // addressing for staged loads (2 float4 per array per thread)
    const int ar0 = tid >> 2,          ac0 = (tid & 3) * 4;          // A row/k-col
    const int ar1 = (tid + 256) >> 2,  ac1 = ((tid + 256) & 3) * 4;
    const int wr0 = tid >> 5,          wc0 = (tid & 31) * 4;         // W k-row/n-col
    const int wr1 = (tid + 256) >> 5,  wc1 = ((tid + 256) & 31) * 4;

    unsigned long long acc[8][4] = {};   // 8 rows x 4 f32x2 col-pairs

    float4 pa0, pa1, pw0, pw1;
    // prefetch tile 0
    pa0 = *(const float4*)&A[(size_t)(m0 + ar0) * K + ac0];
    pa1 = *(const float4*)&A[(size_t)(m0 + ar1) * K + ac1];
    pw0 = *(const float4*)&W[(size_t)wr0 * 128 + wc0];
    pw1 = *(const float4*)&W[(size_t)wr1 * 128 + wc1];

    const int NT = K / 16;
    for (int t = 0; t < NT; t++) {
        // stage regs -> smem (transpose A, optional relu)
        float4 v = pa0;
        if (RELU_A) { v.x=fmaxf(v.x,0.f); v.y=fmaxf(v.y,0.f); v.z=fmaxf(v.z,0.f); v.w=fmaxf(v.w,0.f); }
        As[ac0+0][ar0]=v.x; As[ac0+1][ar0]=v.y; As[ac0+2][ar0]=v.z; As[ac0+3][ar0]=v.w;
        v = pa1;
        if (RELU_A) { v.x=fmaxf(v.x,0.f); v.y=fmaxf(v.y,0.f); v.z=fmaxf(v.z,0.f); v.w=fmaxf(v.w,0.f); }
        As[ac1+0][ar1]=v.x; As[ac1+1][ar1]=v.y; As[ac1+2][ar1]=v.z; As[ac1+3][ar1]=v.w;
        *(float4*)&Bs[wr0][wc0] = pw0;
        *(float4*)&Bs[wr1][wc1] = pw1;
        __syncthreads();

        // prefetch next tile (latency overlapped with compute below)
        if (t + 1 < NT) {
            int k0 = (t + 1) * 16;
            pa0 = *(const float4*)&A[(size_t)(m0 + ar0) * K + k0 + ac0];
            pa1 = *(const float4*)&A[(size_t)(m0 + ar1) * K + k0 + ac1];
            pw0 = *(const float4*)&W[(size_t)(k0 + wr0) * 128 + wc0];
            pw1 = *(const float4*)&W[(size_t)(k0 + wr1) * 128 + wc1];
        }

        #pragma unroll
        for (int kk = 0; kk < 16; kk++) {
            float a[8];
            *(float4*)(a)   = *(const float4*)&As[kk][ty*8];
            *(float4*)(a+4) = *(const float4*)&As[kk][ty*8+4];
            unsigned long long bv[4];
            *(ulonglong2*)(bv)   = *(const ulonglong2*)&Bs[kk][tx*8];
            *(ulonglong2*)(bv+2) = *(const ulonglong2*)&Bs[kk][tx*8+4];
            #pragma unroll
            for (int i = 0; i < 8; i++) {
                unsigned long long av = pack2(a[i]);
                #pragma unroll
                for (int j = 0; j < 4; j++)
                    ffma2(acc[i][j], av, bv[j]);
            }
        }
        __syncthreads();
    }

    #pragma unroll
    for (int i = 0; i < 8; i++) {
        int m = m0 + ty*8 + i;
        float r[8];
        #pragma unroll
        for (int j = 0; j < 4; j++) {
            float2 v = *(float2*)&acc[i][j];
            r[2*j] = v.x; r[2*j+1] = v.y;
        }
        #pragma unroll
        for (int j = 0; j < 8; j += 4) {
            int n = tx*8 + j;
            float4 o;
            o.x = r[j]; o.y = r[j+1]; o.z = r[j+2]; o.w = r[j+3];
            if (bias) {
                o.x += bias[n]; o.y += bias[n+1]; o.z += bias[n+2]; o.w += bias[n+3];
            }
            if (ADD_D) {
                float4 d = *(const float4*)&D[(size_t)m*128 + n];
                o.x += d.x; o.y += d.y; o.z += d.z; o.w += d.w;
            }
            *(float4*)&C[(size_t)m*128 + n] = o;
        }
    }
}

// ---------------- pool reset to -inf (vectorized) ----------------
__global__ void k_pool_neg_inf() {
    int i = blockIdx.x * blockDim.x + threadIdx.x;
    if (i < POOL_N / 4) {
        int4 v; v.x = v.y = v.z = v.w = 0xFF800000;
        ((int4*)g_pool)[i] = v;
    }
}

// ---------------- scatter max of g_net into pools ----------------
__global__ void k_scatter_max() {
    int i = blockIdx.x * blockDim.x + threadIdx.x;   // BT*128
    int t = i >> 7, f = i & 127;
    int b = t >> 15;
    float v = g_net[i];
    #pragma unroll
    for (int k = 0; k < 3; k++) {
        float* addr = &g_pool[(size_t)((k*B + b) * R2 + g_idx[k][t]) * 128 + f];
        if (v >= 0.0f) atomicMax((int*)addr, __float_as_int(v));
        else           atomicMin((unsigned int*)addr, __float_as_uint(v));
    }
}

// ---------------- gather pooled + concat into g_x ----------------
__global__ void k_gather_concat() {
    int i = blockIdx.x * blockDim.x + threadIdx.x;   // BT*128
    int t = i >> 7, f = i & 127;
    int b = t >> 15;
    float s = 0.0f;
    #pragma unroll
    for (int k = 0; k < 3; k++)
        s += g_pool[(size_t)((k*B + b) * R2 + g_idx[k][t]) * 128 + f];
    g_x[(size_t)t*256 + f]       = g_net[i];
    g_x[(size_t)t*256 + 128 + f] = s;
}

// ---------------- zero pool + counts (vectorized) ----------------
__global__ void k_zero() {
    int i = blockIdx.x * blockDim.x + threadIdx.x;
    if (i < POOL_N / 4) {
        float4 z; z.x = z.y = z.z = z.w = 0.0f;
        ((float4*)g_pool)[i] = z;
    }
    if (i < CNT_N) g_cnt[i] = 0.0f;
}

// ---------------- scatter sum of c (g_h) into pools + counts ----------------
__global__ void k_scatter_sum() {
    int i = blockIdx.x * blockDim.x + threadIdx.x;   // BT*128
    int t = i >> 7, f = i & 127;
    int b = t >> 15;
    float v = g_h[i];
    #pragma unroll
    for (int k = 0; k < 3; k++) {
        int cell = g_idx[k][t];
        atomicAdd(&g_pool[(size_t)((k*B + b) * R2 + cell) * 128 + f], v);
        if (f == 0) atomicAdd(&g_cnt[(k*B + b) * R2 + cell], 1.0f);
    }
}

// ---------------- finalize: divide by count, transpose to (3,B,C,R2) ------
__global__ void k_finalize(float* __restrict__ out) {
    int i = blockIdx.x * blockDim.x + threadIdx.x;   // POOL_N, [kb][f][cell]
    if (i >= POOL_N) return;
    int cell = i & (R2 - 1);
    int f    = (i >> 14) & 127;
    int kb   = i >> 21;
    float cnt = g_cnt[kb * R2 + cell];
    float v = g_pool[(size_t)(kb * R2 + cell) * 128 + f] / fmaxf(cnt, 1.0f);
    out[i] = v;    // out layout (3,B,128,R2) with cell fastest == i
}

// ---------------- host orchestration ----------------
extern "C" void kernel_launch(void* const* d_in, const int* in_sizes, int n_in,
                              void* d_out, int out_size) {
    const float* p        = (const float*)d_in[0];
    const float* fc_pos_W = (const float*)d_in[1];
    const float* fc_pos_b = (const float*)d_in[2];
    const float* bW0      = (const float*)d_in[3];  // (5,256,128)
    const float* bb0      = (const float*)d_in[4];  // (5,128)
    const float* bW1      = (const float*)d_in[5];  // (5,128,128)
    const float* bb1      = (const float*)d_in[6];  // (5,128)
    const float* bWs      = (const float*)d_in[7];  // (5,256,128)
    const float* fc_c_W   = (const float*)d_in[8];  // (128,128)
    const float* fc_c_b   = (const float*)d_in[9];  // (128,)
    float* out = (float*)d_out;

    float* gx   = nullptr; cudaGetSymbolAddress((void**)&gx,   g_x);
    float* gh   = nullptr; cudaGetSymbolAddress((void**)&gh,   g_h);
    float* gnet = nullptr; cudaGetSymbolAddress((void**)&gnet, g_net);

    const int TPB = 256;
    const int GEMM_GRID = BT / 128;          // 512

    // indices
    k_index<<<BT / TPB, TPB>>>(p);
    // fc_pos -> g_x (BT,256)
    k_fcpos<<<(BT * 256) / TPB, TPB>>>(p, fc_pos_W, fc_pos_b);

    // block 0 (no pooling)
    k_gemm<256, true,  false><<<GEMM_GRID, TPB>>>(gx, bW0, bb0, nullptr, gh);
    k_gemm<128, true,  false><<<GEMM_GRID, TPB>>>(gh, bW1, bb1, nullptr, gnet);
    k_gemm<256, false, true ><<<GEMM_GRID, TPB>>>(gx, bWs, nullptr, gnet, gnet);

    // blocks 1..4 with pooling
    for (int blk = 1; blk < 5; blk++) {
        k_pool_neg_inf<<<POOL_N / 4 / TPB, TPB>>>();
        k_scatter_max<<<(BT * 128) / TPB, TPB>>>();
        k_gather_concat<<<(BT * 128) / TPB, TPB>>>();
        const float* W0 = bW0 + (size_t)blk * 256 * 128;
        const float* b0 = bb0 + (size_t)blk * 128;
        const float* W1 = bW1 + (size_t)blk * 128 * 128;
        const float* b1 = bb1 + (size_t)blk * 128;
        const float* Ws = bWs + (size_t)blk * 256 * 128;
        k_gemm<256, true,  false><<<GEMM_GRID, TPB>>>(gx, W0, b0, nullptr, gh);
        k_gemm<128, true,  false><<<GEMM_GRID, TPB>>>(gh, W1, b1, nullptr, gnet);
        k_gemm<256, false, true ><<<GEMM_GRID, TPB>>>(gx, Ws, nullptr, gnet, gnet);
    }

    // fc_c -> g_h  (c features)
    k_gemm<128, false, false><<<GEMM_GRID, TPB>>>(gnet, fc_c_W, fc_c_b, nullptr, gh);

    // scatter mean into output
    k_zero<<<POOL_N / 4 / TPB, TPB>>>();
    k_scatter_sum<<<(BT * 128) / TPB, TPB>>>();
    k_finalize<<<POOL_N / TPB, TPB>>>(out);
}

// round 4
// speedup vs baseline: 1.4531x; 1.4210x over previous
#include <cuda_runtime.h>
#include <cuda_bf16.h>
#include <cstdint>

// ---------------- problem constants ----------------
#define B       2
#define T       32768
#define BT      (B*T)           // 65536
#define R2      16384
#define POOL_N  (3*B*R2*128)
#define CNT_N   (3*B*R2)

// ---------------- scratch (device globals; no allocs) ----------------
__device__ float g_x[BT*256];
__device__ float g_h[BT*128];
__device__ float g_net[BT*128];
__device__ float g_pool[POOL_N];
__device__ float g_cnt[CNT_N];
__device__ int   g_idx[3][BT];
__device__ __nv_bfloat16 g_wt[851968];   // pre-split weights hi/lo planes, [N=128][K]

// ---------------- helpers ----------------
__device__ __forceinline__ uint32_t smem_u32(const void* p) {
    uint32_t a;
    asm("{ .reg .u64 t; cvta.to.shared.u64 t, %1; cvt.u32.u64 %0, t; }" : "=r"(a) : "l"(p));
    return a;
}
__device__ __forceinline__ void ldsm4(uint32_t& r0, uint32_t& r1, uint32_t& r2, uint32_t& r3,
                                      uint32_t a) {
    asm volatile("ldmatrix.sync.aligned.m8n8.x4.shared.b16 {%0,%1,%2,%3}, [%4];"
        : "=r"(r0), "=r"(r1), "=r"(r2), "=r"(r3) : "r"(a));
}
__device__ __forceinline__ void mma16816(float* c, const uint32_t* a, uint32_t b0, uint32_t b1) {
    asm volatile("mma.sync.aligned.m16n8k16.row.col.f32.bf16.bf16.f32 "
        "{%0,%1,%2,%3}, {%4,%5,%6,%7}, {%8,%9}, {%0,%1,%2,%3};"
        : "+f"(c[0]), "+f"(c[1]), "+f"(c[2]), "+f"(c[3])
        : "r"(a[0]), "r"(a[1]), "r"(a[2]), "r"(a[3]), "r"(b0), "r"(b1));
}
__device__ __forceinline__ uint32_t b2u(__nv_bfloat162 v) {
    return *reinterpret_cast<uint32_t*>(&v);
}

// ---------------- index computation (matches jax exactly) ----------------
__global__ void k_index(const float* __restrict__ p) {
    int t = blockIdx.x * blockDim.x + threadIdx.x;
    if (t >= BT) return;
    float x = p[t*3+0], y = p[t*3+1], z = p[t*3+2];
    float cu[3] = {x, x, y};
    float cv[3] = {z, y, z};
    const float hi = (float)(1.0 - 1e-5);
    #pragma unroll
    for (int k = 0; k < 3; k++) {
        float u = cu[k] / 1.101f + 0.5f;
        float v = cv[k] / 1.101f + 0.5f;
        u = fminf(fmaxf(u, 0.0f), hi);
        v = fminf(fmaxf(v, 0.0f), hi);
        g_idx[k][t] = (int)(u * 128.0f) + 128 * (int)(v * 128.0f);
    }
}

// ---------------- fc_pos ----------------
__global__ void k_fcpos(const float* __restrict__ p, const float* __restrict__ W,
                        const float* __restrict__ bias) {
    int i = blockIdx.x * blockDim.x + threadIdx.x;   // BT*256
    int t = i >> 8, n = i & 255;
    float p0 = p[t*3+0], p1 = p[t*3+1], p2 = p[t*3+2];
    g_x[i] = p0 * W[n] + p1 * W[256+n] + p2 * W[512+n] + bias[n];
}

// ---------------- weight pre-split: fp32 [K,128] -> bf16 hi/lo planes [128][K] ----
__global__ void k_wsplit(const float* __restrict__ W0, const float* __restrict__ W1,
                         const float* __restrict__ Ws, const float* __restrict__ fcW) {
    int i = blockIdx.x * blockDim.x + threadIdx.x;
    if (i >= 425984) return;
    const float* src; int K, base, e;
    if (i < 163840)       { int blk = i / 32768;            e = i % 32768; K = 256; src = W0 + blk*32768; base = blk*65536; }
    else if (i < 245760)  { int j = i - 163840; int blk = j / 16384; e = j % 16384; K = 128; src = W1 + blk*16384; base = 327680 + blk*32768; }
    else if (i < 409600)  { int j = i - 245760; int blk = j / 32768; e = j % 32768; K = 256; src = Ws + blk*32768; base = 491520 + blk*65536; }
    else                  { e = i - 409600; K = 128; src = fcW; base = 819200; }
    int n = e / K, k = e % K;
    float v = src[(size_t)k * 128 + n];
    __nv_bfloat16 hi = __float2bfloat16(v);
    __nv_bfloat16 lo = __float2bfloat16(v - __bfloat162float(hi));
    g_wt[base + (size_t)n * K + k]           = hi;
    g_wt[base + (size_t)128 * K + n * K + k] = lo;
}

// ---------------- bf16-split GEMM via mma.sync ----------------
// C[M,128] = f(A[M,K]) @ W[K,128] (+bias) (+D)
// SMEM planes: bf16 [128][136] (272B row stride, 16B aligned, ldmatrix conflict-free)
#define SA        136
#define PLANE_B   (128 * SA * 2)       // 34816 bytes
#define OFF_AH    1024
#define OFF_AL    (OFF_AH + PLANE_B)
#define OFF_BH    (OFF_AL + PLANE_B)
#define OFF_BL    (OFF_BH + PLANE_B)
#define GEMM_SMEM (OFF_BL + PLANE_B)   // 140288

template<int K, bool RELU_A, bool ADD_D>
__global__ __launch_bounds__(256, 1)
void k_gemm_mma(const float* __restrict__ A,
                const __nv_bfloat16* __restrict__ Whi,
                const __nv_bfloat16* __restrict__ Wlo,
                const float* __restrict__ bias,
                const float* __restrict__ Dres,
                float* __restrict__ C) {
    extern __shared__ __align__(16) char smem[];
    float* biasS = (float*)smem;
    const int tid  = threadIdx.x, lane = tid & 31, wid = tid >> 5;
    const int m0   = blockIdx.x * 128;
    const int wm   = (wid & 3) * 32;     // warp M origin in tile
    const int wn   = (wid >> 2) * 64;    // warp N origin in tile
    const uint32_t sb = smem_u32(smem);

    if (tid < 128) biasS[tid] = bias ? bias[tid] : 0.0f;

    float acc[2][8][4] = {};             // [mf][nf][quad]

    // ldmatrix per-lane base rows/cols
    const int aRow   = wm + (lane & 15);
    const int aCoff  = (lane >> 4) * 8;
    const int bRow   = wn + (lane & 7) + ((lane >> 4) << 3);
    const int bCoff  = ((lane >> 3) & 1) * 8;

    const int NCH = K / 128;
    for (int ch = 0; ch < NCH; ch++) {
        const int K0 = ch * 128;
        __syncthreads();                 // previous chunk's ldmatrix reads done
        // --- A: load fp32, relu, hi/lo split, store bf16 planes
        for (int i = tid; i < 128 * 32; i += 256) {
            int r = i >> 5, c4 = (i & 31) << 2;
            float4 v = *(const float4*)&A[(size_t)(m0 + r) * K + K0 + c4];
            if (RELU_A) {
                v.x = fmaxf(v.x, 0.f); v.y = fmaxf(v.y, 0.f);
                v.z = fmaxf(v.z, 0.f); v.w = fmaxf(v.w, 0.f);
            }
            __nv_bfloat162 h01, h23, l01, l23;
            h01.x = __float2bfloat16(v.x); h01.y = __float2bfloat16(v.y);
            h23.x = __float2bfloat16(v.z); h23.y = __float2bfloat16(v.w);
            l01.x = __float2bfloat16(v.x - __bfloat162float(h01.x));
            l01.y = __float2bfloat16(v.y - __bfloat162float(h01.y));
            l23.x = __float2bfloat16(v.z - __bfloat162float(h23.x));
            l23.y = __float2bfloat16(v.w - __bfloat162float(h23.y));
            uint32_t off = (uint32_t)r * (SA*2) + (uint32_t)c4 * 2;
            uint2 hp; hp.x = b2u(h01); hp.y = b2u(h23);
            uint2 lp; lp.x = b2u(l01); lp.y = b2u(l23);
            *(uint2*)(smem + OFF_AH + off) = hp;
            *(uint2*)(smem + OFF_AL + off) = lp;
        }
        // --- B: copy pre-split bf16 [n][k] rows
        for (int i = tid; i < 128 * 16; i += 256) {
            int r = i >> 4, c8 = (i & 15) << 3;
            uint32_t off = (uint32_t)r * (SA*2) + (uint32_t)c8 * 2;
            *(uint4*)(smem + OFF_BH + off) = *(const uint4*)&Whi[(size_t)r * K + K0 + c8];
            *(uint4*)(smem + OFF_BL + off) = *(const uint4*)&Wlo[(size_t)r * K + K0 + c8];
        }
        __syncthreads();

        for (int ks = 0; ks < 128; ks += 16) {
            uint32_t ah0[4], ah1[4], al0[4], al1[4];
            {
                uint32_t c0 = (uint32_t)(ks + aCoff) * 2;
                uint32_t r0 = (uint32_t)aRow * (SA*2);
                uint32_t r1 = (uint32_t)(aRow + 16) * (SA*2);
                ldsm4(ah0[0], ah0[1], ah0[2], ah0[3], sb + OFF_AH + r0 + c0);
                ldsm4(ah1[0], ah1[1], ah1[2], ah1[3], sb + OFF_AH + r1 + c0);
                ldsm4(al0[0], al0[1], al0[2], al0[3], sb + OFF_AL + r0 + c0);
                ldsm4(al1[0], al1[1], al1[2], al1[3], sb + OFF_AL + r1 + c0);
            }
            uint32_t bh[8][2], bl[8][2];
            #pragma unroll
            for (int nf2 = 0; nf2 < 4; nf2++) {
                uint32_t addr = (uint32_t)(bRow + nf2*16) * (SA*2) + (uint32_t)(ks + bCoff) * 2;
                ldsm4(bh[nf2*2][0], bh[nf2*2][1], bh[nf2*2+1][0], bh[nf2*2+1][1],
                      sb + OFF_BH + addr);
                ldsm4(bl[nf2*2][0], bl[nf2*2][1], bl[nf2*2+1][0], bl[nf2*2+1][1],
                      sb + OFF_BL + addr);
            }
            #pragma unroll
            for (int nf = 0; nf < 8; nf++) {
                mma16816(acc[0][nf], ah0, bh[nf][0], bh[nf][1]);
                mma16816(acc[1][nf], ah1, bh[nf][0], bh[nf][1]);
                mma16816(acc[0][nf], ah0, bl[nf][0], bl[nf][1]);
                mma16816(acc[1][nf], ah1, bl[nf][0], bl[nf][1]);
                mma16816(acc[0][nf], al0, bh[nf][0], bh[nf][1]);
                mma16816(acc[1][nf], al1, bh[nf][0], bh[nf][1]);
            }
        }
    }

    // --- epilogue: bias + optional residual, write fp32
    #pragma unroll
    for (int mf = 0; mf < 2; mf++) {
        #pragma unroll
        for (int nf = 0; nf < 8; nf++) {
            int m = m0 + wm + mf*16 + (lane >> 2);
            int n = wn + nf*8 + (lane & 3) * 2;
            float2 v0, v1;
            v0.x = acc[mf][nf][0] + biasS[n];
            v0.y = acc[mf][nf][1] + biasS[n+1];
            v1.x = acc[mf][nf][2] + biasS[n];
            v1.y = acc[mf][nf][3] + biasS[n+1];
            if (ADD_D) {
                float2 d0 = *(const float2*)&Dres[(size_t)m * 128 + n];
                float2 d1 = *(const float2*)&Dres[(size_t)(m+8) * 128 + n];
                v0.x += d0.x; v0.y += d0.y; v1.x += d1.x; v1.y += d1.y;
            }
            *(float2*)&C[(size_t)m * 128 + n]     = v0;
            *(float2*)&C[(size_t)(m+8) * 128 + n] = v1;
        }
    }
}

// ---------------- pooling / scatter path (unchanged, passing) ----------------
__global__ void k_pool_neg_inf() {
    int i = blockIdx.x * blockDim.x + threadIdx.x;
    if (i < POOL_N / 4) {
        int4 v; v.x = v.y = v.z = v.w = 0xFF800000;
        ((int4*)g_pool)[i] = v;
    }
}

__global__ void k_scatter_max() {
    int i = blockIdx.x * blockDim.x + threadIdx.x;   // BT*128
    int t = i >> 7, f = i & 127;
    int b = t >> 15;
    float v = g_net[i];
    #pragma unroll
    for (int k = 0; k < 3; k++) {
        float* addr = &g_pool[(size_t)((k*B + b) * R2 + g_idx[k][t]) * 128 + f];
        if (v >= 0.0f) atomicMax((int*)addr, __float_as_int(v));
        else           atomicMin((unsigned int*)addr, __float_as_uint(v));
    }
}

__global__ void k_gather_concat() {
    int i = blockIdx.x * blockDim.x + threadIdx.x;   // BT*128
    int t = i >> 7, f = i & 127;
    int b = t >> 15;
    float s = 0.0f;
    #pragma unroll
    for (int k = 0; k < 3; k++)
        s += g_pool[(size_t)((k*B + b) * R2 + g_idx[k][t]) * 128 + f];
    g_x[(size_t)t*256 + f]       = g_net[i];
    g_x[(size_t)t*256 + 128 + f] = s;
}

__global__ void k_zero() {
    int i = blockIdx.x * blockDim.x + threadIdx.x;
    if (i < POOL_N / 4) {
        float4 z; z.x = z.y = z.z = z.w = 0.0f;
        ((float4*)g_pool)[i] = z;
    }
    if (i < CNT_N) g_cnt[i] = 0.0f;
}

__global__ void k_scatter_sum() {
    int i = blockIdx.x * blockDim.x + threadIdx.x;   // BT*128
    int t = i >> 7, f = i & 127;
    int b = t >> 15;
    float v = g_h[i];
    #pragma unroll
    for (int k = 0; k < 3; k++) {
        int cell = g_idx[k][t];
        atomicAdd(&g_pool[(size_t)((k*B + b) * R2 + cell) * 128 + f], v);
        if (f == 0) atomicAdd(&g_cnt[(k*B + b) * R2 + cell], 1.0f);
    }
}

__global__ void k_finalize(float* __restrict__ out) {
    int i = blockIdx.x * blockDim.x + threadIdx.x;   // POOL_N, [kb][f][cell]
    if (i >= POOL_N) return;
    int cell = i & (R2 - 1);
    int f    = (i >> 14) & 127;
    int kb   = i >> 21;
    float cnt = g_cnt[kb * R2 + cell];
    out[i] = g_pool[(size_t)(kb * R2 + cell) * 128 + f] / fmaxf(cnt, 1.0f);
}

// ---------------- host orchestration ----------------
extern "C" void kernel_launch(void* const* d_in, const int* in_sizes, int n_in,
                              void* d_out, int out_size) {
    const float* p        = (const float*)d_in[0];
    const float* fc_pos_W = (const float*)d_in[1];
    const float* fc_pos_b = (const float*)d_in[2];
    const float* bW0      = (const float*)d_in[3];  // (5,256,128)
    const float* bb0      = (const float*)d_in[4];
    const float* bW1      = (const float*)d_in[5];  // (5,128,128)
    const float* bb1      = (const float*)d_in[6];
    const float* bWs      = (const float*)d_in[7];  // (5,256,128)
    const float* fc_c_W   = (const float*)d_in[8];  // (128,128)
    const float* fc_c_b   = (const float*)d_in[9];
    float* out = (float*)d_out;

    float* gx   = nullptr; cudaGetSymbolAddress((void**)&gx,   g_x);
    float* gh   = nullptr; cudaGetSymbolAddress((void**)&gh,   g_h);
    float* gnet = nullptr; cudaGetSymbolAddress((void**)&gnet, g_net);
    __nv_bfloat16* wt = nullptr; cudaGetSymbolAddress((void**)&wt, g_wt);

    cudaFuncSetAttribute(k_gemm_mma<256, true,  false>, cudaFuncAttributeMaxDynamicSharedMemorySize, GEMM_SMEM);
    cudaFuncSetAttribute(k_gemm_mma<128, true,  false>, cudaFuncAttributeMaxDynamicSharedMemorySize, GEMM_SMEM);
    cudaFuncSetAttribute(k_gemm_mma<256, false, true >, cudaFuncAttributeMaxDynamicSharedMemorySize, GEMM_SMEM);
    cudaFuncSetAttribute(k_gemm_mma<128, false, false>, cudaFuncAttributeMaxDynamicSharedMemorySize, GEMM_SMEM);

    const int TPB = 256;
    const int GG  = BT / 128;   // 512

    k_index<<<BT / TPB, TPB>>>(p);
    k_wsplit<<<(425984 + TPB - 1) / TPB, TPB>>>(bW0, bW1, bWs, fc_c_W);
    k_fcpos<<<(BT * 256) / TPB, TPB>>>(p, fc_pos_W, fc_pos_b);

    auto W0hi = [&](int b){ return wt + (size_t)b * 65536; };
    auto W0lo = [&](int b){ return wt + (size_t)b * 65536 + 32768; };
    auto W1hi = [&](int b){ return wt + 327680 + (size_t)b * 32768; };
    auto W1lo = [&](int b){ return wt + 327680 + (size_t)b * 32768 + 16384; };
    auto WShi = [&](int b){ return wt + 491520 + (size_t)b * 65536; };
    auto WSlo = [&](int b){ return wt + 491520 + (size_t)b * 65536 + 32768; };
    const __nv_bfloat16* FChi = wt + 819200;
    const __nv_bfloat16* FClo = wt + 819200 + 16384;

    // block 0 (no pooling)
    k_gemm_mma<256, true,  false><<<GG, TPB, GEMM_SMEM>>>(gx, W0hi(0), W0lo(0), bb0,     nullptr, gh);
    k_gemm_mma<128, true,  false><<<GG, TPB, GEMM_SMEM>>>(gh, W1hi(0), W1lo(0), bb1,     nullptr, gnet);
    k_gemm_mma<256, false, true ><<<GG, TPB, GEMM_SMEM>>>(gx, WShi(0), WSlo(0), nullptr, gnet,    gnet);

    for (int blk = 1; blk < 5; blk++) {
        k_pool_neg_inf<<<POOL_N / 4 / TPB, TPB>>>();
        k_scatter_max<<<(BT * 128) / TPB, TPB>>>();
        k_gather_concat<<<(BT * 128) / TPB, TPB>>>();
        k_gemm_mma<256, true,  false><<<GG, TPB, GEMM_SMEM>>>(gx, W0hi(blk), W0lo(blk), bb0 + blk*128, nullptr, gh);
        k_gemm_mma<128, true,  false><<<GG, TPB, GEMM_SMEM>>>(gh, W1hi(blk), W1lo(blk), bb1 + blk*128, nullptr, gnet);
        k_gemm_mma<256, false, true ><<<GG, TPB, GEMM_SMEM>>>(gx, WShi(blk), WSlo(blk), nullptr,       gnet,    gnet);
    }

    // fc_c
    k_gemm_mma<128, false, false><<<GG, TPB, GEMM_SMEM>>>(gnet, FChi, FClo, fc_c_b, nullptr, gh);

    // scatter mean into output
    k_zero<<<POOL_N / 4 / TPB, TPB>>>();
    k_scatter_sum<<<(BT * 128) / TPB, TPB>>>();
    k_finalize<<<POOL_N / TPB, TPB>>>(out);
}

// round 5
// speedup vs baseline: 1.7323x; 1.1922x over previous
#include <cuda_runtime.h>
#include <cuda_bf16.h>
#include <cstdint>

// ---------------- problem constants ----------------
#define B       2
#define T       32768
#define BT      (B*T)           // 65536
#define R2      16384
#define POOL_N  (3*B*R2*128)
#define CNT_N   (3*B*R2)

// ---------------- scratch (device globals; no allocs) ----------------
__device__ float g_x[BT*256];       // fc_pos out (256-wide) / later pooled sums (128-wide)
__device__ float g_h[BT*128];
__device__ float g_net[BT*128];
__device__ float g_pool[POOL_N];    // pool planes; head also reused as dx scratch between poolings
__device__ float g_cnt[CNT_N];
__device__ int   g_idx[3][BT];
__device__ __nv_bfloat16 g_wt[851968];

// ---------------- helpers ----------------
__device__ __forceinline__ uint32_t smem_u32(const void* p) {
    uint32_t a;
    asm("{ .reg .u64 t; cvta.to.shared.u64 t, %1; cvt.u32.u64 %0, t; }" : "=r"(a) : "l"(p));
    return a;
}
__device__ __forceinline__ void ldsm4(uint32_t& r0, uint32_t& r1, uint32_t& r2, uint32_t& r3,
                                      uint32_t a) {
    asm volatile("ldmatrix.sync.aligned.m8n8.x4.shared.b16 {%0,%1,%2,%3}, [%4];"
        : "=r"(r0), "=r"(r1), "=r"(r2), "=r"(r3) : "r"(a));
}
__device__ __forceinline__ void mma16816(float* c, const uint32_t* a, uint32_t b0, uint32_t b1) {
    asm volatile("mma.sync.aligned.m16n8k16.row.col.f32.bf16.bf16.f32 "
        "{%0,%1,%2,%3}, {%4,%5,%6,%7}, {%8,%9}, {%0,%1,%2,%3};"
        : "+f"(c[0]), "+f"(c[1]), "+f"(c[2]), "+f"(c[3])
        : "r"(a[0]), "r"(a[1]), "r"(a[2]), "r"(a[3]), "r"(b0), "r"(b1));
}
__device__ __forceinline__ uint32_t b2u(__nv_bfloat162 v) {
    return *reinterpret_cast<uint32_t*>(&v);
}

// ---------------- index computation (matches jax exactly) ----------------
__global__ void k_index(const float* __restrict__ p) {
    int t = blockIdx.x * blockDim.x + threadIdx.x;
    if (t >= BT) return;
    float x = p[t*3+0], y = p[t*3+1], z = p[t*3+2];
    float cu[3] = {x, x, y};
    float cv[3] = {z, y, z};
    const float hi = (float)(1.0 - 1e-5);
    #pragma unroll
    for (int k = 0; k < 3; k++) {
        float u = cu[k] / 1.101f + 0.5f;
        float v = cv[k] / 1.101f + 0.5f;
        u = fminf(fmaxf(u, 0.0f), hi);
        v = fminf(fmaxf(v, 0.0f), hi);
        g_idx[k][t] = (int)(u * 128.0f) + 128 * (int)(v * 128.0f);
    }
}

// ---------------- fc_pos ----------------
__global__ void k_fcpos(const float* __restrict__ p, const float* __restrict__ W,
                        const float* __restrict__ bias) {
    int i = blockIdx.x * blockDim.x + threadIdx.x;   // BT*256
    int t = i >> 8, n = i & 255;
    float p0 = p[t*3+0], p1 = p[t*3+1], p2 = p[t*3+2];
    g_x[i] = p0 * W[n] + p1 * W[256+n] + p2 * W[512+n] + bias[n];
}

// ---------------- weight pre-split ----------------
__global__ void k_wsplit(const float* __restrict__ W0, const float* __restrict__ W1,
                         const float* __restrict__ Ws, const float* __restrict__ fcW) {
    int i = blockIdx.x * blockDim.x + threadIdx.x;
    if (i >= 425984) return;
    const float* src; int K, base, e;
    if (i < 163840)       { int blk = i / 32768;            e = i % 32768; K = 256; src = W0 + blk*32768; base = blk*65536; }
    else if (i < 245760)  { int j = i - 163840; int blk = j / 16384; e = j % 16384; K = 128; src = W1 + blk*16384; base = 327680 + blk*32768; }
    else if (i < 409600)  { int j = i - 245760; int blk = j / 32768; e = j % 32768; K = 256; src = Ws + blk*32768; base = 491520 + blk*65536; }
    else                  { e = i - 409600; K = 128; src = fcW; base = 819200; }
    int n = e / K, k = e % K;
    float v = src[(size_t)k * 128 + n];
    __nv_bfloat16 hi = __float2bfloat16(v);
    __nv_bfloat16 lo = __float2bfloat16(v - __bfloat162float(hi));
    g_wt[base + (size_t)n * K + k]           = hi;
    g_wt[base + (size_t)128 * K + n * K + k] = lo;
}

// ---------------- bf16-split GEMM via mma.sync, K-chunk=64, 2 CTAs/SM -------
#define SA        72
#define PLANE_B   (128 * SA * 2)       // 18432
#define OFF_AH    1024
#define OFF_AL    (OFF_AH + PLANE_B)
#define OFF_BH    (OFF_AL + PLANE_B)
#define OFF_BL    (OFF_BH + PLANE_B)
#define GEMM_SMEM (OFF_BL + PLANE_B)   // 74752

template<int NCH, bool RELU_A, bool ADD_D>
__global__ __launch_bounds__(256, 2)
void k_gemm_mma(const float* __restrict__ A1, int lda1,
                const float* __restrict__ A2, int lda2,
                const __nv_bfloat16* __restrict__ Whi,
                const __nv_bfloat16* __restrict__ Wlo,
                const float* __restrict__ bias,
                const float* __restrict__ Dres,
                float* __restrict__ C) {
    extern __shared__ __align__(16) char smem[];
    float* biasS = (float*)smem;
    const int tid  = threadIdx.x, lane = tid & 31, wid = tid >> 5;
    const int m0   = blockIdx.x * 128;
    const int wm   = (wid & 3) * 32;
    const int wn   = (wid >> 2) * 64;
    const uint32_t sb = smem_u32(smem);
    const int K = NCH * 64;

    if (tid < 128) biasS[tid] = bias ? bias[tid] : 0.0f;

    float acc[2][8][4] = {};

    const int aRow  = wm + (lane & 15);
    const int aCoff = (lane >> 4) * 8;
    const int bRow  = wn + (lane & 7) + ((lane >> 4) << 3);
    const int bCoff = ((lane >> 3) & 1) * 8;

    #pragma unroll
    for (int ch = 0; ch < NCH; ch++) {
        const int K0 = ch * 64;
        const float* Asrc = (K0 < 128) ? A1 + K0 : A2 + (K0 - 128);
        const int    lda  = (K0 < 128) ? lda1 : lda2;
        __syncthreads();
        for (int i = tid; i < 128 * 16; i += 256) {
            int r = i >> 4, c4 = (i & 15) << 2;
            float4 v = *(const float4*)&Asrc[(size_t)(m0 + r) * lda + c4];
            if (RELU_A) {
                v.x = fmaxf(v.x, 0.f); v.y = fmaxf(v.y, 0.f);
                v.z = fmaxf(v.z, 0.f); v.w = fmaxf(v.w, 0.f);
            }
            __nv_bfloat162 h01, h23, l01, l23;
            h01.x = __float2bfloat16(v.x); h01.y = __float2bfloat16(v.y);
            h23.x = __float2bfloat16(v.z); h23.y = __float2bfloat16(v.w);
            l01.x = __float2bfloat16(v.x - __bfloat162float(h01.x));
            l01.y = __float2bfloat16(v.y - __bfloat162float(h01.y));
            l23.x = __float2bfloat16(v.z - __bfloat162float(h23.x));
            l23.y = __float2bfloat16(v.w - __bfloat162float(h23.y));
            uint32_t off = (uint32_t)r * (SA*2) + (uint32_t)c4 * 2;
            uint2 hp; hp.x = b2u(h01); hp.y = b2u(h23);
            uint2 lp; lp.x = b2u(l01); lp.y = b2u(l23);
            *(uint2*)(smem + OFF_AH + off) = hp;
            *(uint2*)(smem + OFF_AL + off) = lp;
        }
        for (int i = tid; i < 128 * 8; i += 256) {
            int r = i >> 3, c8 = (i & 7) << 3;
            uint32_t off = (uint32_t)r * (SA*2) + (uint32_t)c8 * 2;
            *(uint4*)(smem + OFF_BH + off) = *(const uint4*)&Whi[(size_t)r * K + K0 + c8];
            *(uint4*)(smem + OFF_BL + off) = *(const uint4*)&Wlo[(size_t)r * K + K0 + c8];
        }
        __syncthreads();

        #pragma unroll
        for (int ks = 0; ks < 64; ks += 16) {
            uint32_t ah0[4], ah1[4], al0[4], al1[4];
            {
                uint32_t c0 = (uint32_t)(ks + aCoff) * 2;
                uint32_t r0 = (uint32_t)aRow * (SA*2);
                uint32_t r1 = (uint32_t)(aRow + 16) * (SA*2);
                ldsm4(ah0[0], ah0[1], ah0[2], ah0[3], sb + OFF_AH + r0 + c0);
                ldsm4(ah1[0], ah1[1], ah1[2], ah1[3], sb + OFF_AH + r1 + c0);
                ldsm4(al0[0], al0[1], al0[2], al0[3], sb + OFF_AL + r0 + c0);
                ldsm4(al1[0], al1[1], al1[2], al1[3], sb + OFF_AL + r1 + c0);
            }
            uint32_t bh[8][2], bl[8][2];
            #pragma unroll
            for (int nf2 = 0; nf2 < 4; nf2++) {
                uint32_t addr = (uint32_t)(bRow + nf2*16) * (SA*2) + (uint32_t)(ks + bCoff) * 2;
                ldsm4(bh[nf2*2][0], bh[nf2*2][1], bh[nf2*2+1][0], bh[nf2*2+1][1],
                      sb + OFF_BH + addr);
                ldsm4(bl[nf2*2][0], bl[nf2*2][1], bl[nf2*2+1][0], bl[nf2*2+1][1],
                      sb + OFF_BL + addr);
            }
            #pragma unroll
            for (int nf = 0; nf < 8; nf++) {
                mma16816(acc[0][nf], ah0, bh[nf][0], bh[nf][1]);
                mma16816(acc[1][nf], ah1, bh[nf][0], bh[nf][1]);
                mma16816(acc[0][nf], ah0, bl[nf][0], bl[nf][1]);
                mma16816(acc[1][nf], ah1, bl[nf][0], bl[nf][1]);
                mma16816(acc[0][nf], al0, bh[nf][0], bh[nf][1]);
                mma16816(acc[1][nf], al1, bh[nf][0], bh[nf][1]);
            }
        }
    }

    #pragma unroll
    for (int mf = 0; mf < 2; mf++) {
        #pragma unroll
        for (int nf = 0; nf < 8; nf++) {
            int m = m0 + wm + mf*16 + (lane >> 2);
            int n = wn + nf*8 + (lane & 3) * 2;
            float2 v0, v1;
            v0.x = acc[mf][nf][0] + biasS[n];
            v0.y = acc[mf][nf][1] + biasS[n+1];
            v1.x = acc[mf][nf][2] + biasS[n];
            v1.y = acc[mf][nf][3] + biasS[n+1];
            if (ADD_D) {
                float2 d0 = *(const float2*)&Dres[(size_t)m * 128 + n];
                float2 d1 = *(const float2*)&Dres[(size_t)(m+8) * 128 + n];
                v0.x += d0.x; v0.y += d0.y; v1.x += d1.x; v1.y += d1.y;
            }
            *(float2*)&C[(size_t)m * 128 + n]     = v0;
            *(float2*)&C[(size_t)(m+8) * 128 + n] = v1;
        }
    }
}

// ---------------- pooling / scatter path ----------------
__global__ void k_pool_neg_inf() {
    int i = blockIdx.x * blockDim.x + threadIdx.x;
    if (i < POOL_N / 4) {
        int4 v; v.x = v.y = v.z = v.w = 0xFF800000;
        ((int4*)g_pool)[i] = v;
    }
}

__global__ void k_scatter_max() {
    int i = blockIdx.x * blockDim.x + threadIdx.x;   // BT*128
    int t = i >> 7, f = i & 127;
    int b = t >> 15;
    float v = g_net[i];
    #pragma unroll
    for (int k = 0; k < 3; k++) {
        float* addr = &g_pool[(size_t)((k*B + b) * R2 + g_idx[k][t]) * 128 + f];
        if (v >= 0.0f) atomicMax((int*)addr, __float_as_int(v));
        else           atomicMin((unsigned int*)addr, __float_as_uint(v));
    }
}

__global__ void k_gather() {
    int i = blockIdx.x * blockDim.x + threadIdx.x;   // BT*128
    int t = i >> 7, f = i & 127;
    int b = t >> 15;
    float s = 0.0f;
    #pragma unroll
    for (int k = 0; k < 3; k++)
        s += g_pool[(size_t)((k*B + b) * R2 + g_idx[k][t]) * 128 + f];
    g_x[(size_t)t*128 + f] = s;
}

__global__ void k_zero() {
    int i = blockIdx.x * blockDim.x + threadIdx.x;
    if (i < POOL_N / 4) {
        float4 z; z.x = z.y = z.z = z.w = 0.0f;
        ((float4*)g_pool)[i] = z;
    }
    if (i < CNT_N) g_cnt[i] = 0.0f;
}

__global__ void k_scatter_sum() {
    int i = blockIdx.x * blockDim.x + threadIdx.x;   // BT*128
    int t = i >> 7, f = i & 127;
    int b = t >> 15;
    float v = g_h[i];
    #pragma unroll
    for (int k = 0; k < 3; k++) {
        int cell = g_idx[k][t];
        atomicAdd(&g_pool[(size_t)((k*B + b) * R2 + cell) * 128 + f], v);
        if (f == 0) atomicAdd(&g_cnt[(k*B + b) * R2 + cell], 1.0f);
    }
}

__global__ void k_finalize(float* __restrict__ out) {
    int i = blockIdx.x * blockDim.x + threadIdx.x;   // POOL_N, [kb][f][cell]
    if (i >= POOL_N) return;
    int cell = i & (R2 - 1);
    int f    = (i >> 14) & 127;
    int kb   = i >> 21;
    float cnt = g_cnt[kb * R2 + cell];
    out[i] = g_pool[(size_t)(kb * R2 + cell) * 128 + f] / fmaxf(cnt, 1.0f);
}

// ---------------- host orchestration ----------------
extern "C" void kernel_launch(void* const* d_in, const int* in_sizes, int n_in,
                              void* d_out, int out_size) {
    const float* p        = (const float*)d_in[0];
    const float* fc_pos_W = (const float*)d_in[1];
    const float* fc_pos_b = (const float*)d_in[2];
    const float* bW0      = (const float*)d_in[3];
    const float* bb0      = (const float*)d_in[4];
    const float* bW1      = (const float*)d_in[5];
    const float* bb1      = (const float*)d_in[6];
    const float* bWs      = (const float*)d_in[7];
    const float* fc_c_W   = (const float*)d_in[8];
    const float* fc_c_b   = (const float*)d_in[9];
    float* out = (float*)d_out;

    float* gx   = nullptr; cudaGetSymbolAddress((void**)&gx,   g_x);
    float* gh   = nullptr; cudaGetSymbolAddress((void**)&gh,   g_h);
    float* gnet = nullptr; cudaGetSymbolAddress((void**)&gnet, g_net);
    float* gpool= nullptr; cudaGetSymbolAddress((void**)&gpool,g_pool);
    __nv_bfloat16* wt = nullptr; cudaGetSymbolAddress((void**)&wt, g_wt);
    float* gdx = gpool;   // dx scratch: head of g_pool (reset before every pool use)

    cudaFuncSetAttribute(k_gemm_mma<4, true,  false>, cudaFuncAttributeMaxDynamicSharedMemorySize, GEMM_SMEM);
    cudaFuncSetAttribute(k_gemm_mma<2, true,  false>, cudaFuncAttributeMaxDynamicSharedMemorySize, GEMM_SMEM);
    cudaFuncSetAttribute(k_gemm_mma<4, false, true >, cudaFuncAttributeMaxDynamicSharedMemorySize, GEMM_SMEM);
    cudaFuncSetAttribute(k_gemm_mma<2, false, false>, cudaFuncAttributeMaxDynamicSharedMemorySize, GEMM_SMEM);

    const int TPB = 256;
    const int GG  = BT / 128;   // 512

    k_index<<<BT / TPB, TPB>>>(p);
    k_wsplit<<<(425984 + TPB - 1) / TPB, TPB>>>(bW0, bW1, bWs, fc_c_W);
    k_fcpos<<<(BT * 256) / TPB, TPB>>>(p, fc_pos_W, fc_pos_b);

    auto W0hi = [&](int b){ return wt + (size_t)b * 65536; };
    auto W0lo = [&](int b){ return wt + (size_t)b * 65536 + 32768; };
    auto W1hi = [&](int b){ return wt + 327680 + (size_t)b * 32768; };
    auto W1lo = [&](int b){ return wt + 327680 + (size_t)b * 32768 + 16384; };
    auto WShi = [&](int b){ return wt + 491520 + (size_t)b * 65536; };
    auto WSlo = [&](int b){ return wt + 491520 + (size_t)b * 65536 + 32768; };
    const __nv_bfloat16* FChi = wt + 819200;
    const __nv_bfloat16* FClo = wt + 819200 + 16384;

    // block 0: input g_x (BT x 256)
    k_gemm_mma<4, true,  false><<<GG, TPB, GEMM_SMEM>>>(gx, 256, gx + 128, 256, W0hi(0), W0lo(0), bb0,     nullptr, gh);
    k_gemm_mma<2, true,  false><<<GG, TPB, GEMM_SMEM>>>(gh, 128, nullptr, 0,    W1hi(0), W1lo(0), bb1,     nullptr, gdx);
    k_gemm_mma<4, false, true ><<<GG, TPB, GEMM_SMEM>>>(gx, 256, gx + 128, 256, WShi(0), WSlo(0), nullptr, gdx,     gnet);

    for (int blk = 1; blk < 5; blk++) {
        k_pool_neg_inf<<<POOL_N / 4 / TPB, TPB>>>();
        k_scatter_max<<<(BT * 128) / TPB, TPB>>>();
        k_gather<<<(BT * 128) / TPB, TPB>>>();
        k_gemm_mma<4, true,  false><<<GG, TPB, GEMM_SMEM>>>(gnet, 128, gx, 128, W0hi(blk), W0lo(blk), bb0 + blk*128, nullptr, gh);
        k_gemm_mma<2, true,  false><<<GG, TPB, GEMM_SMEM>>>(gh, 128, nullptr, 0, W1hi(blk), W1lo(blk), bb1 + blk*128, nullptr, gdx);
        k_gemm_mma<4, false, true ><<<GG, TPB, GEMM_SMEM>>>(gnet, 128, gx, 128, WShi(blk), WSlo(blk), nullptr,        gdx,     gnet);
    }

    // fc_c
    k_gemm_mma<2, false, false><<<GG, TPB, GEMM_SMEM>>>(gnet, 128, nullptr, 0, FChi, FClo, fc_c_b, nullptr, gh);

    // scatter mean into output
    k_zero<<<POOL_N / 4 / TPB, TPB>>>();
    k_scatter_sum<<<(BT * 128) / TPB, TPB>>>();
    k_finalize<<<POOL_N / TPB, TPB>>>(out);
}

// round 6
// speedup vs baseline: 1.8729x; 1.0812x over previous
#include <cuda_runtime.h>
#include <cuda_bf16.h>
#include <cstdint>

// ---------------- problem constants ----------------
#define B       2
#define T       32768
#define BT      (B*T)           // 65536
#define R2      16384
#define POOL_N  (3*B*R2*128)    // 12,582,912 floats
#define CNT_N   (3*B*R2)

// ---------------- scratch (device globals; no allocs) ----------------
__device__ float g_dx[BT*128];      // dx scratch
__device__ float g_h[BT*128];       // hidden
__device__ float g_net[BT*128];     // block output
__device__ float g_poolA[POOL_N];   // ping-pong max pools; A reused as mean pool at end
__device__ float g_poolB[POOL_N];
__device__ float g_cnt[CNT_N];
__device__ int   g_idx[3][BT];
__device__ __nv_bfloat16 g_wt[851968];

// ---------------- helpers ----------------
__device__ __forceinline__ uint32_t smem_u32(const void* p) {
    uint32_t a;
    asm("{ .reg .u64 t; cvta.to.shared.u64 t, %1; cvt.u32.u64 %0, t; }" : "=r"(a) : "l"(p));
    return a;
}
__device__ __forceinline__ void ldsm4(uint32_t& r0, uint32_t& r1, uint32_t& r2, uint32_t& r3,
                                      uint32_t a) {
    asm volatile("ldmatrix.sync.aligned.m8n8.x4.shared.b16 {%0,%1,%2,%3}, [%4];"
        : "=r"(r0), "=r"(r1), "=r"(r2), "=r"(r3) : "r"(a));
}
__device__ __forceinline__ void mma16816(float* c, const uint32_t* a, uint32_t b0, uint32_t b1) {
    asm volatile("mma.sync.aligned.m16n8k16.row.col.f32.bf16.bf16.f32 "
        "{%0,%1,%2,%3}, {%4,%5,%6,%7}, {%8,%9}, {%0,%1,%2,%3};"
        : "+f"(c[0]), "+f"(c[1]), "+f"(c[2]), "+f"(c[3])
        : "r"(a[0]), "r"(a[1]), "r"(a[2]), "r"(a[3]), "r"(b0), "r"(b1));
}
__device__ __forceinline__ uint32_t b2u(__nv_bfloat162 v) {
    return *reinterpret_cast<uint32_t*>(&v);
}
__device__ __forceinline__ void amax(float* addr, float v) {
    if (v >= 0.0f) atomicMax((int*)addr, __float_as_int(v));
    else           atomicMin((unsigned int*)addr, __float_as_uint(v));
}

// ---------------- index computation (matches jax exactly) ----------------
__global__ void k_index(const float* __restrict__ p) {
    int t = blockIdx.x * blockDim.x + threadIdx.x;
    if (t >= BT) return;
    float x = p[t*3+0], y = p[t*3+1], z = p[t*3+2];
    float cu[3] = {x, x, y};
    float cv[3] = {z, y, z};
    const float hi = (float)(1.0 - 1e-5);
    #pragma unroll
    for (int k = 0; k < 3; k++) {
        float u = cu[k] / 1.101f + 0.5f;
        float v = cv[k] / 1.101f + 0.5f;
        u = fminf(fmaxf(u, 0.0f), hi);
        v = fminf(fmaxf(v, 0.0f), hi);
        g_idx[k][t] = (int)(u * 128.0f) + 128 * (int)(v * 128.0f);
    }
}

// ---------------- weight pre-split ----------------
__global__ void k_wsplit(const float* __restrict__ W0, const float* __restrict__ W1,
                         const float* __restrict__ Ws, const float* __restrict__ fcW) {
    int i = blockIdx.x * blockDim.x + threadIdx.x;
    if (i >= 425984) return;
    const float* src; int K, base, e;
    if (i < 163840)       { int blk = i / 32768;            e = i % 32768; K = 256; src = W0 + blk*32768; base = blk*65536; }
    else if (i < 245760)  { int j = i - 163840; int blk = j / 16384; e = j % 16384; K = 128; src = W1 + blk*16384; base = 327680 + blk*32768; }
    else if (i < 409600)  { int j = i - 245760; int blk = j / 32768; e = j % 32768; K = 256; src = Ws + blk*32768; base = 491520 + blk*65536; }
    else                  { e = i - 409600; K = 128; src = fcW; base = 819200; }
    int n = e / K, k = e % K;
    float v = src[(size_t)k * 128 + n];
    __nv_bfloat16 hi = __float2bfloat16(v);
    __nv_bfloat16 lo = __float2bfloat16(v - __bfloat162float(hi));
    g_wt[base + (size_t)n * K + k]           = hi;
    g_wt[base + (size_t)128 * K + n * K + k] = lo;
}

// ---------------- fused bf16-split GEMM via mma.sync ----------------
// ASRC: 0 = A1 only; 1 = fcpos on-the-fly (K=256); 2 = A1 (k<128) + pool gather (k>=128)
#define SA        72
#define PLANE_B   (128 * SA * 2)
#define OFF_AH    1024
#define OFF_AL    (OFF_AH + PLANE_B)
#define OFF_BH    (OFF_AL + PLANE_B)
#define OFF_BL    (OFF_BH + PLANE_B)
#define GEMM_SMEM (OFF_BL + PLANE_B)   // 74752

template<int NCH, int ASRC, bool RELU_A, bool ADD_D, bool SCATTER, bool SCATSUM, bool WRITE_C>
__global__ __launch_bounds__(256, 2)
void k_gemm_mma(const float* __restrict__ A1, int lda1,
                const float* __restrict__ P,       // points (ASRC1)
                const float* __restrict__ fcW,     // (ASRC1)
                const float* __restrict__ fcb,     // (ASRC1)
                const float* __restrict__ poolIn,  // (ASRC2)
                float* __restrict__ poolOut,       // (SCATTER/SCATSUM)
                float* __restrict__ cnt,           // (SCATSUM)
                const __nv_bfloat16* __restrict__ Whi,
                const __nv_bfloat16* __restrict__ Wlo,
                const float* __restrict__ bias,
                const float* __restrict__ Dres,
                float* __restrict__ C) {
    extern __shared__ __align__(16) char smem[];
    float* biasS = (float*)smem;
    const int tid  = threadIdx.x, lane = tid & 31, wid = tid >> 5;
    const int m0   = blockIdx.x * 128;
    const int wm   = (wid & 3) * 32;
    const int wn   = (wid >> 2) * 64;
    const uint32_t sb = smem_u32(smem);
    const int K = NCH * 64;

    if (tid < 128) biasS[tid] = bias ? bias[tid] : 0.0f;

    float acc[2][8][4] = {};

    const int aRow  = wm + (lane & 15);
    const int aCoff = (lane >> 4) * 8;
    const int bRow  = wn + (lane & 7) + ((lane >> 4) << 3);
    const int bCoff = ((lane >> 3) & 1) * 8;

    #pragma unroll
    for (int ch = 0; ch < NCH; ch++) {
        const int K0 = ch * 64;
        __syncthreads();
        // ---- A phase: 2 waves of 4 MLP-batched quads
        #pragma unroll
        for (int w = 0; w < 2; w++) {
            float4 vb[4];
            #pragma unroll
            for (int j = 0; j < 4; j++) {
                int i = tid + (w*4 + j) * 256;
                int r = i >> 4, c4 = (i & 15) << 2;
                int m = m0 + r;
                if (ASRC == 1) {
                    float p0 = P[m*3+0], p1 = P[m*3+1], p2 = P[m*3+2];
                    int cg = K0 + c4;
                    float4 v;
                    v.x = fmaf(p0, fcW[cg+0], fmaf(p1, fcW[256+cg+0], fmaf(p2, fcW[512+cg+0], fcb[cg+0])));
                    v.y = fmaf(p0, fcW[cg+1], fmaf(p1, fcW[256+cg+1], fmaf(p2, fcW[512+cg+1], fcb[cg+1])));
                    v.z = fmaf(p0, fcW[cg+2], fmaf(p1, fcW[256+cg+2], fmaf(p2, fcW[512+cg+2], fcb[cg+2])));
                    v.w = fmaf(p0, fcW[cg+3], fmaf(p1, fcW[256+cg+3], fmaf(p2, fcW[512+cg+3], fcb[cg+3])));
                    vb[j] = v;
                } else if (ASRC == 2 && K0 >= 128) {
                    int b = m >> 15;
                    int c0 = (K0 - 128) + c4;
                    float4 s; s.x = s.y = s.z = s.w = 0.0f;
                    #pragma unroll
                    for (int k = 0; k < 3; k++) {
                        int cell = g_idx[k][m];
                        float4 pv = *(const float4*)&poolIn[((size_t)((k*B + b)*R2) + cell)*128 + c0];
                        s.x += pv.x; s.y += pv.y; s.z += pv.z; s.w += pv.w;
                    }
                    vb[j] = s;
                } else {
                    vb[j] = *(const float4*)&A1[(size_t)m * lda1 + K0 + c4];
                }
            }
            #pragma unroll
            for (int j = 0; j < 4; j++) {
                int i = tid + (w*4 + j) * 256;
                int r = i >> 4, c4 = (i & 15) << 2;
                float4 v = vb[j];
                if (RELU_A) {
                    v.x = fmaxf(v.x, 0.f); v.y = fmaxf(v.y, 0.f);
                    v.z = fmaxf(v.z, 0.f); v.w = fmaxf(v.w, 0.f);
                }
                __nv_bfloat162 h01, h23, l01, l23;
                h01.x = __float2bfloat16(v.x); h01.y = __float2bfloat16(v.y);
                h23.x = __float2bfloat16(v.z); h23.y = __float2bfloat16(v.w);
                l01.x = __float2bfloat16(v.x - __bfloat162float(h01.x));
                l01.y = __float2bfloat16(v.y - __bfloat162float(h01.y));
                l23.x = __float2bfloat16(v.z - __bfloat162float(h23.x));
                l23.y = __float2bfloat16(v.w - __bfloat162float(h23.y));
                uint32_t off = (uint32_t)r * (SA*2) + (uint32_t)c4 * 2;
                uint2 hp; hp.x = b2u(h01); hp.y = b2u(h23);
                uint2 lp; lp.x = b2u(l01); lp.y = b2u(l23);
                *(uint2*)(smem + OFF_AH + off) = hp;
                *(uint2*)(smem + OFF_AL + off) = lp;
            }
        }
        // ---- B phase: 4 MLP-batched rows
        {
            uint4 wh[4], wl[4];
            #pragma unroll
            for (int j = 0; j < 4; j++) {
                int i = tid + j * 256;
                int r = i >> 3, c8 = (i & 7) << 3;
                wh[j] = *(const uint4*)&Whi[(size_t)r * K + K0 + c8];
                wl[j] = *(const uint4*)&Wlo[(size_t)r * K + K0 + c8];
            }
            #pragma unroll
            for (int j = 0; j < 4; j++) {
                int i = tid + j * 256;
                int r = i >> 3, c8 = (i & 7) << 3;
                uint32_t off = (uint32_t)r * (SA*2) + (uint32_t)c8 * 2;
                *(uint4*)(smem + OFF_BH + off) = wh[j];
                *(uint4*)(smem + OFF_BL + off) = wl[j];
            }
        }
        __syncthreads();

        #pragma unroll
        for (int ks = 0; ks < 64; ks += 16) {
            uint32_t ah0[4], ah1[4], al0[4], al1[4];
            {
                uint32_t c0 = (uint32_t)(ks + aCoff) * 2;
                uint32_t r0 = (uint32_t)aRow * (SA*2);
                uint32_t r1 = (uint32_t)(aRow + 16) * (SA*2);
                ldsm4(ah0[0], ah0[1], ah0[2], ah0[3], sb + OFF_AH + r0 + c0);
                ldsm4(ah1[0], ah1[1], ah1[2], ah1[3], sb + OFF_AH + r1 + c0);
                ldsm4(al0[0], al0[1], al0[2], al0[3], sb + OFF_AL + r0 + c0);
                ldsm4(al1[0], al1[1], al1[2], al1[3], sb + OFF_AL + r1 + c0);
            }
            uint32_t bh[8][2], bl[8][2];
            #pragma unroll
            for (int nf2 = 0; nf2 < 4; nf2++) {
                uint32_t addr = (uint32_t)(bRow + nf2*16) * (SA*2) + (uint32_t)(ks + bCoff) * 2;
                ldsm4(bh[nf2*2][0], bh[nf2*2][1], bh[nf2*2+1][0], bh[nf2*2+1][1],
                      sb + OFF_BH + addr);
                ldsm4(bl[nf2*2][0], bl[nf2*2][1], bl[nf2*2+1][0], bl[nf2*2+1][1],
                      sb + OFF_BL + addr);
            }
            #pragma unroll
            for (int nf = 0; nf < 8; nf++) {
                mma16816(acc[0][nf], ah0, bh[nf][0], bh[nf][1]);
                mma16816(acc[1][nf], ah1, bh[nf][0], bh[nf][1]);
                mma16816(acc[0][nf], ah0, bl[nf][0], bl[nf][1]);
                mma16816(acc[1][nf], ah1, bl[nf][0], bl[nf][1]);
                mma16816(acc[0][nf], al0, bh[nf][0], bh[nf][1]);
                mma16816(acc[1][nf], al1, bh[nf][0], bh[nf][1]);
            }
        }
    }

    // ---- epilogue
    #pragma unroll
    for (int mf = 0; mf < 2; mf++) {
        const int m  = m0 + wm + mf*16 + (lane >> 2);
        const int bb = m >> 15;
        int cellA[3], cellB[3];
        if (SCATTER || SCATSUM) {
            #pragma unroll
            for (int k = 0; k < 3; k++) {
                cellA[k] = g_idx[k][m];
                cellB[k] = g_idx[k][m + 8];
            }
        }
        #pragma unroll
        for (int nf = 0; nf < 8; nf++) {
            int n = wn + nf*8 + (lane & 3) * 2;
            float2 v0, v1;
            v0.x = acc[mf][nf][0] + biasS[n];
            v0.y = acc[mf][nf][1] + biasS[n+1];
            v1.x = acc[mf][nf][2] + biasS[n];
            v1.y = acc[mf][nf][3] + biasS[n+1];
            if (ADD_D) {
                float2 d0 = *(const float2*)&Dres[(size_t)m * 128 + n];
                float2 d1 = *(const float2*)&Dres[(size_t)(m+8) * 128 + n];
                v0.x += d0.x; v0.y += d0.y; v1.x += d1.x; v1.y += d1.y;
            }
            if (WRITE_C) {
                *(float2*)&C[(size_t)m * 128 + n]     = v0;
                *(float2*)&C[(size_t)(m+8) * 128 + n] = v1;
            }
            if (SCATTER) {
                #pragma unroll
                for (int k = 0; k < 3; k++) {
                    float* pA = &poolOut[((size_t)((k*B + bb)*R2) + cellA[k])*128 + n];
                    float* pB = &poolOut[((size_t)((k*B + bb)*R2) + cellB[k])*128 + n];
                    amax(pA,     v0.x); amax(pA + 1, v0.y);
                    amax(pB,     v1.x); amax(pB + 1, v1.y);
                }
            }
            if (SCATSUM) {
                #pragma unroll
                for (int k = 0; k < 3; k++) {
                    float* pA = &poolOut[((size_t)((k*B + bb)*R2) + cellA[k])*128 + n];
                    float* pB = &poolOut[((size_t)((k*B + bb)*R2) + cellB[k])*128 + n];
                    atomicAdd(pA,     v0.x); atomicAdd(pA + 1, v0.y);
                    atomicAdd(pB,     v1.x); atomicAdd(pB + 1, v1.y);
                    if (n == 0) {
                        atomicAdd(&cnt[(k*B + bb)*R2 + cellA[k]], 1.0f);
                        atomicAdd(&cnt[(k*B + bb)*R2 + cellB[k]], 1.0f);
                    }
                }
            }
        }
    }
}

// ---------------- utility kernels ----------------
__global__ void k_pool_neg_inf(float* __restrict__ pool) {
    int i = blockIdx.x * blockDim.x + threadIdx.x;
    if (i < POOL_N / 4) {
        int4 v; v.x = v.y = v.z = v.w = 0xFF800000;
        ((int4*)pool)[i] = v;
    }
}

__global__ void k_zero(float* __restrict__ pool) {
    int i = blockIdx.x * blockDim.x + threadIdx.x;
    if (i < POOL_N / 4) {
        float4 z; z.x = z.y = z.z = z.w = 0.0f;
        ((float4*)pool)[i] = z;
    }
    if (i < CNT_N) g_cnt[i] = 0.0f;
}

__global__ void k_finalize(const float* __restrict__ pool, float* __restrict__ out) {
    int i = blockIdx.x * blockDim.x + threadIdx.x;   // [kb][f][cell]
    if (i >= POOL_N) return;
    int cell = i & (R2 - 1);
    int f    = (i >> 14) & 127;
    int kb   = i >> 21;
    float cnt = g_cnt[kb * R2 + cell];
    out[i] = pool[(size_t)(kb * R2 + cell) * 128 + f] / fmaxf(cnt, 1.0f);
}

// ---------------- host orchestration ----------------
extern "C" void kernel_launch(void* const* d_in, const int* in_sizes, int n_in,
                              void* d_out, int out_size) {
    const float* p        = (const float*)d_in[0];
    const float* fc_pos_W = (const float*)d_in[1];
    const float* fc_pos_b = (const float*)d_in[2];
    const float* bW0      = (const float*)d_in[3];
    const float* bb0      = (const float*)d_in[4];
    const float* bW1      = (const float*)d_in[5];
    const float* bb1      = (const float*)d_in[6];
    const float* bWs      = (const float*)d_in[7];
    const float* fc_c_W   = (const float*)d_in[8];
    const float* fc_c_b   = (const float*)d_in[9];
    float* out = (float*)d_out;

    float* gdx  = nullptr; cudaGetSymbolAddress((void**)&gdx,  g_dx);
    float* gh   = nullptr; cudaGetSymbolAddress((void**)&gh,   g_h);
    float* gnet = nullptr; cudaGetSymbolAddress((void**)&gnet, g_net);
    float* pA   = nullptr; cudaGetSymbolAddress((void**)&pA,   g_poolA);
    float* pB   = nullptr; cudaGetSymbolAddress((void**)&pB,   g_poolB);
    float* gcnt = nullptr; cudaGetSymbolAddress((void**)&gcnt, g_cnt);
    __nv_bfloat16* wt = nullptr; cudaGetSymbolAddress((void**)&wt, g_wt);

    // GEMM variants
    auto* gW0f = k_gemm_mma<4, 1, true,  false, false, false, true>;   // W0 blk0 (fcpos A)
    auto* gW1  = k_gemm_mma<2, 0, true,  false, false, false, true>;   // W1 all
    auto* gWsf = k_gemm_mma<4, 1, false, true,  true,  false, true>;   // Ws blk0 (fcpos A, scatter)
    auto* gW0  = k_gemm_mma<4, 2, true,  false, false, false, true>;   // W0 blk1-4 (gather A2)
    auto* gWsS = k_gemm_mma<4, 2, false, true,  true,  false, true>;   // Ws blk1-3 (gather, scatter)
    auto* gWsL = k_gemm_mma<4, 2, false, true,  false, false, true>;   // Ws blk4 (gather, no scatter)
    auto* gFC  = k_gemm_mma<2, 0, false, false, false, true,  false>;  // fc_c (scatter-sum, no C)

    cudaFuncSetAttribute(gW0f, cudaFuncAttributeMaxDynamicSharedMemorySize, GEMM_SMEM);
    cudaFuncSetAttribute(gW1,  cudaFuncAttributeMaxDynamicSharedMemorySize, GEMM_SMEM);
    cudaFuncSetAttribute(gWsf, cudaFuncAttributeMaxDynamicSharedMemorySize, GEMM_SMEM);
    cudaFuncSetAttribute(gW0,  cudaFuncAttributeMaxDynamicSharedMemorySize, GEMM_SMEM);
    cudaFuncSetAttribute(gWsS, cudaFuncAttributeMaxDynamicSharedMemorySize, GEMM_SMEM);
    cudaFuncSetAttribute(gWsL, cudaFuncAttributeMaxDynamicSharedMemorySize, GEMM_SMEM);
    cudaFuncSetAttribute(gFC,  cudaFuncAttributeMaxDynamicSharedMemorySize, GEMM_SMEM);

    const int TPB = 256;
    const int GG  = BT / 128;   // 512
    const int RG  = POOL_N / 4 / TPB;

    k_index<<<BT / TPB, TPB>>>(p);
    k_wsplit<<<(425984 + TPB - 1) / TPB, TPB>>>(bW0, bW1, bWs, fc_c_W);

    auto W0hi = [&](int b){ return wt + (size_t)b * 65536; };
    auto W0lo = [&](int b){ return wt + (size_t)b * 65536 + 32768; };
    auto W1hi = [&](int b){ return wt + 327680 + (size_t)b * 32768; };
    auto W1lo = [&](int b){ return wt + 327680 + (size_t)b * 32768 + 16384; };
    auto WShi = [&](int b){ return wt + 491520 + (size_t)b * 65536; };
    auto WSlo = [&](int b){ return wt + 491520 + (size_t)b * 65536 + 32768; };
    const __nv_bfloat16* FChi = wt + 819200;
    const __nv_bfloat16* FClo = wt + 819200 + 16384;

    // block 0: A = fcpos(p) on the fly; Ws epilogue scatters net -> poolA
    k_pool_neg_inf<<<RG, TPB>>>(pA);
    gW0f<<<GG, TPB, GEMM_SMEM>>>(nullptr, 0, p, fc_pos_W, fc_pos_b, nullptr, nullptr, nullptr,
                                 W0hi(0), W0lo(0), bb0, nullptr, gh);
    gW1 <<<GG, TPB, GEMM_SMEM>>>(gh, 128, nullptr, nullptr, nullptr, nullptr, nullptr, nullptr,
                                 W1hi(0), W1lo(0), bb1, nullptr, gdx);
    gWsf<<<GG, TPB, GEMM_SMEM>>>(nullptr, 0, p, fc_pos_W, fc_pos_b, nullptr, pA, nullptr,
                                 WShi(0), WSlo(0), nullptr, gdx, gnet);

    // blocks 1..4: gather from poolIn in A-phase; Ws scatters to poolOut (ping-pong)
    float* pin  = pA;
    float* pout = pB;
    for (int blk = 1; blk < 5; blk++) {
        if (blk < 4) k_pool_neg_inf<<<RG, TPB>>>(pout);
        gW0<<<GG, TPB, GEMM_SMEM>>>(gnet, 128, nullptr, nullptr, nullptr, pin, nullptr, nullptr,
                                    W0hi(blk), W0lo(blk), bb0 + blk*128, nullptr, gh);
        gW1<<<GG, TPB, GEMM_SMEM>>>(gh, 128, nullptr, nullptr, nullptr, nullptr, nullptr, nullptr,
                                    W1hi(blk), W1lo(blk), bb1 + blk*128, nullptr, gdx);
        if (blk < 4) {
            gWsS<<<GG, TPB, GEMM_SMEM>>>(gnet, 128, nullptr, nullptr, nullptr, pin, pout, nullptr,
                                         WShi(blk), WSlo(blk), nullptr, gdx, gnet);
        } else {
            gWsL<<<GG, TPB, GEMM_SMEM>>>(gnet, 128, nullptr, nullptr, nullptr, pin, nullptr, nullptr,
                                         WShi(blk), WSlo(blk), nullptr, gdx, gnet);
        }
        float* tmp = pin; pin = pout; pout = tmp;
    }

    // fc_c with fused scatter-mean accumulation into poolA (free after blk3 gathers)
    k_zero<<<RG, TPB>>>(pA);
    gFC<<<GG, TPB, GEMM_SMEM>>>(gnet, 128, nullptr, nullptr, nullptr, nullptr, pA, gcnt,
                                FChi, FClo, fc_c_b, nullptr, nullptr);

    k_finalize<<<(POOL_N + TPB - 1) / TPB, TPB>>>(pA, out);
}